// round 5
// baseline (speedup 1.0000x reference)
#include <cuda_runtime.h>
#include <cstdint>

// VQ nearest-codebook lookup via 3xTF32 mma.sync distance GEMM.
//   z_e_x: [16,2048,256] f32 -> N=32768 rows, D=256
//   embedding: [1024,256] f32 -> K=1024 codes
// d_out (f32): z_q_x [N*D] @0, z_q_x_bar [N*D] @8388608, indices [N] @16777216
// argmin_k(||c||^2 - 2 x.c) == argmax_k(x.c - ||c||^2/2).
// Raw f32 tiles staged via cp.async (3-deep ring); tf32 hi/lo split done in
// registers after ldmatrix; scores get the norm term in a scalar epilogue.

#define NTOK   32768
#define DDIM   256
#define KCODE  1024
#define BM     256          // rows per CTA
#define BN     128          // codes per tile
#define KS     16           // k per stage
#define NST    16           // stages per tile
#define NTILE  8            // KCODE / BN
#define NG     (NTILE * NST)
#define PITCH  20           // floats per k16 row (80B, bank/ldsm-clean)

#define OUT_BAR   8388608
#define OUT_IDX  16777216

// float offsets into dynamic smem
#define AS_F      0                     // A ring: 3 x [256][20]
#define A_STAGE  (BM * PITCH)           // 5120
#define BS_F     (3 * A_STAGE)          // 15360; B ring: 3 x [128][20]
#define B_STAGE  (BN * PITCH)           // 2560
#define CN_F     (BS_F + 3 * B_STAGE)   // 23040
#define DYN_FLOATS (CN_F + KCODE)       // 24064
#define DYN_SMEM (DYN_FLOATS * 4)

__device__ float g_cnorm[KCODE];

// ---------------------------------------------------------------------------
__device__ __forceinline__ uint32_t smem_u32(const void* p) {
    uint32_t a;
    asm("{ .reg .u64 t; cvta.to.shared.u64 t, %1; cvt.u32.u64 %0, t; }"
        : "=r"(a) : "l"(p));
    return a;
}
__device__ __forceinline__ float tf32_rna(float x) {
    uint32_t r;
    asm("cvt.rna.tf32.f32 %0, %1;" : "=r"(r) : "f"(x));
    return __uint_as_float(r);
}
#define LDSM4(r, addr) \
    asm volatile("ldmatrix.sync.aligned.m8n8.x4.shared.b16 {%0,%1,%2,%3}, [%4];" \
        : "=r"((r)[0]), "=r"((r)[1]), "=r"((r)[2]), "=r"((r)[3]) : "r"(addr))

#define CP_ASYNC16(dst, src) \
    asm volatile("cp.async.cg.shared.global [%0], [%1], 16;" :: "r"(dst), "l"(src))
#define CP_COMMIT() asm volatile("cp.async.commit_group;" ::: "memory")
#define CP_WAIT1()  asm volatile("cp.async.wait_group 1;" ::: "memory")

__device__ __forceinline__ void mma_tf32(float* c, const uint32_t* a, const uint32_t* b) {
    asm volatile(
        "mma.sync.aligned.m16n8k8.row.col.f32.tf32.tf32.f32 "
        "{%0,%1,%2,%3}, {%4,%5,%6,%7}, {%8,%9}, {%0,%1,%2,%3};"
        : "+f"(c[0]), "+f"(c[1]), "+f"(c[2]), "+f"(c[3])
        : "r"(a[0]), "r"(a[1]), "r"(a[2]), "r"(a[3]), "r"(b[0]), "r"(b[1]));
}

__device__ __forceinline__ void split4(const uint32_t raw[4], uint32_t h[4], uint32_t l[4]) {
    #pragma unroll
    for (int i = 0; i < 4; ++i) {
        float v = __uint_as_float(raw[i]);
        float hf = tf32_rna(v);
        h[i] = __float_as_uint(hf);
        l[i] = __float_as_uint(tf32_rna(v - hf));
    }
}

// ---------------------------------------------------------------------------
__global__ void cnorm_kernel(const float* __restrict__ emb) {
    int warp = (blockIdx.x * blockDim.x + threadIdx.x) >> 5;
    int lane = threadIdx.x & 31;
    if (warp >= KCODE) return;
    const float* row = emb + (size_t)warp * DDIM;
    float s = 0.f;
    #pragma unroll
    for (int k = lane; k < DDIM; k += 32) { float v = row[k]; s += v * v; }
    #pragma unroll
    for (int o = 16; o; o >>= 1) s += __shfl_xor_sync(0xffffffffu, s, o);
    if (lane == 0) g_cnorm[warp] = s;
}

// ---------------------------------------------------------------------------
// 256 threads = 8 warps in 4(m) x 2(n); warp tile 64 rows x 64 codes.
// ---------------------------------------------------------------------------
__global__ __launch_bounds__(256)
void vq_mma_kernel(const float* __restrict__ x,
                   const float* __restrict__ emb,
                   float* __restrict__ out) {
    extern __shared__ float dsm[];
    __shared__ float sV[2][BM];
    __shared__ int   sI[2][BM];
    __shared__ int   bidx_s[BM];

    const int tid = threadIdx.x;
    const int wid = tid >> 5;
    const int L   = tid & 31;
    const int rowBase = blockIdx.x * BM;
    const int mbase = (wid >> 1) * 64;
    const int nbase = (wid & 1) * 64;

    const uint32_t SB = smem_u32(dsm);

    // ldmatrix lane geometry (byte offsets within a stage tile)
    const int aRow = (L & 7) + 8 * ((L >> 3) & 1);
    const int aK   = (L >> 4) * 16;
    const int bRow = (L & 7) + 8 * ((L >> 4) & 1);
    const int bK   = ((L >> 3) & 1) * 16;
    const uint32_t aBase = (uint32_t)((mbase + aRow) * 80 + aK);
    const uint32_t bBase = (uint32_t)((nbase + bRow) * 80 + bK);

    // cp.async loader geometry
    const int lRow = tid >> 2;          // 0..63
    const int lKg  = (tid & 3) * 4;     // float offset within k16

    // cnorm table into smem (once)
    #pragma unroll
    for (int i = 0; i < 4; ++i) dsm[CN_F + tid + 256 * i] = g_cnorm[tid + 256 * i];

    float bV[8];
    int   bI[8];
    #pragma unroll
    for (int i = 0; i < 8; ++i) { bV[i] = -3.4e38f; bI[i] = 0x7fffffff; }

    // ---- issue cp.async for global stage sidx into ring slot sidx%3 ----
    #define ISSUE_STAGE(sidx) do { \
        if ((sidx) < NG) { \
            const int _t  = (sidx) >> 4; \
            const int _ko = ((sidx) & 15) * KS + lKg; \
            const int _sl = (sidx) % 3; \
            const uint32_t _ab = SB + (AS_F + _sl * A_STAGE) * 4; \
            const uint32_t _bb = SB + (BS_F + _sl * B_STAGE) * 4; \
            _Pragma("unroll") \
            for (int _i = 0; _i < 4; ++_i) { \
                int _r = lRow + 64 * _i; \
                CP_ASYNC16(_ab + (uint32_t)(_r * PITCH + lKg) * 4, \
                           x + (size_t)(rowBase + _r) * DDIM + _ko); \
            } \
            _Pragma("unroll") \
            for (int _i = 0; _i < 2; ++_i) { \
                int _r = lRow + 64 * _i; \
                CP_ASYNC16(_bb + (uint32_t)(_r * PITCH + lKg) * 4, \
                           emb + (size_t)(_t * BN + _r) * DDIM + _ko); \
            } \
        } \
        CP_COMMIT(); \
    } while (0)

    ISSUE_STAGE(0);
    ISSUE_STAGE(1);

    float acc[4][8][4];
    #pragma unroll
    for (int f = 0; f < 4; ++f)
        #pragma unroll
        for (int n = 0; n < 8; ++n)
            #pragma unroll
            for (int e = 0; e < 4; ++e) acc[f][n][e] = 0.f;

    for (int g = 0; g < NG; ++g) {
        CP_WAIT1();             // stage g resident
        __syncthreads();        // all warps done with stage g-1 -> slot (g+2)%3 free
        ISSUE_STAGE(g + 2);

        const int sl = g % 3;
        const uint32_t AB = SB + (AS_F + sl * A_STAGE) * 4;
        const uint32_t BB = SB + (BS_F + sl * B_STAGE) * 4;

        #pragma unroll
        for (int kk = 0; kk < 2; ++kk) {
            const uint32_t kof = (uint32_t)(kk * 32);
            uint32_t araw[4][4], ah[4][4], al[4][4];
            uint32_t braw[4][4], bh[4][4], bl[4][4];
            #pragma unroll
            for (int f = 0; f < 4; ++f) {
                LDSM4(araw[f], AB + aBase + f * 1280 + kof);
                split4(araw[f], ah[f], al[f]);
            }
            #pragma unroll
            for (int q = 0; q < 4; ++q) {
                LDSM4(braw[q], BB + bBase + q * 1280 + kof);
                split4(braw[q], bh[q], bl[q]);
            }
            #pragma unroll
            for (int f = 0; f < 4; ++f)
                #pragma unroll
                for (int n = 0; n < 8; ++n)
                    mma_tf32(acc[f][n], ah[f], &bh[n >> 1][(n & 1) * 2]);
            #pragma unroll
            for (int f = 0; f < 4; ++f)
                #pragma unroll
                for (int n = 0; n < 8; ++n)
                    mma_tf32(acc[f][n], ah[f], &bl[n >> 1][(n & 1) * 2]);
            #pragma unroll
            for (int f = 0; f < 4; ++f)
                #pragma unroll
                for (int n = 0; n < 8; ++n)
                    mma_tf32(acc[f][n], al[f], &bh[n >> 1][(n & 1) * 2]);
        }

        // ---- tile epilogue: fold norms, update per-lane argmax ----
        if ((g & 15) == 15) {
            const int cb = (g >> 4) * BN;
            #pragma unroll
            for (int n = 0; n < 8; ++n) {
                #pragma unroll
                for (int e = 0; e < 2; ++e) {
                    const int ci = cb + nbase + 8 * n + 2 * (L & 3) + e;
                    const float hc = -0.5f * dsm[CN_F + ci];
                    #pragma unroll
                    for (int f = 0; f < 4; ++f) {
                        float vlo = acc[f][n][e]     + hc;
                        float vhi = acc[f][n][2 + e] + hc;
                        if (vlo > bV[2 * f])     { bV[2 * f] = vlo;     bI[2 * f] = ci; }
                        if (vhi > bV[2 * f + 1]) { bV[2 * f + 1] = vhi; bI[2 * f + 1] = ci; }
                    }
                }
            }
            if (g + 1 < NG) {
                #pragma unroll
                for (int f = 0; f < 4; ++f)
                    #pragma unroll
                    for (int n = 0; n < 8; ++n)
                        #pragma unroll
                        for (int e = 0; e < 4; ++e) acc[f][n][e] = 0.f;
            }
        }
    }

    // quad reduce (lanes sharing L>>2 cover the same rows)
    #pragma unroll
    for (int i = 0; i < 8; ++i) {
        float v = bV[i]; int idx = bI[i];
        #pragma unroll
        for (int o = 1; o < 4; o <<= 1) {
            float vo = __shfl_xor_sync(0xffffffffu, v, o);
            int   io = __shfl_xor_sync(0xffffffffu, idx, o);
            if (vo > v || (vo == v && io < idx)) { v = vo; idx = io; }
        }
        bV[i] = v; bI[i] = idx;
    }
    if ((L & 3) == 0) {
        const int wn = wid & 1;
        #pragma unroll
        for (int f = 0; f < 4; ++f)
            #pragma unroll
            for (int h = 0; h < 2; ++h) {
                int row = mbase + 16 * f + 8 * h + (L >> 2);
                sV[wn][row] = bV[2 * f + h];
                sI[wn][row] = bI[2 * f + h];
            }
    }
    __syncthreads();

    // combine the two n-warps, publish winners
    {
        float v0 = sV[0][tid], v1 = sV[1][tid];
        int   i0 = sI[0][tid], i1 = sI[1][tid];
        int idx = (v1 > v0 || (v1 == v0 && i1 < i0)) ? i1 : i0;
        bidx_s[tid] = idx;
        out[OUT_IDX + rowBase + tid] = (float)idx;
    }
    __syncthreads();

    // gather codes, write z_q_x and z_q_x_bar
    const float4* emb4 = (const float4*)emb;
    float4* o4 = (float4*)out;
    #pragma unroll 4
    for (int it = 0; it < 64; ++it) {
        int g = tid + it * 256;          // 0..16383
        int m = g >> 6;
        int q = g & 63;
        int code = bidx_s[m];
        float4 v = emb4[(size_t)code * 64 + q];
        size_t off = (size_t)(rowBase + m) * 64 + q;
        o4[off] = v;
        o4[off + (OUT_BAR / 4)] = v;
    }
}

// ---------------------------------------------------------------------------
extern "C" void kernel_launch(void* const* d_in, const int* in_sizes, int n_in,
                              void* d_out, int out_size) {
    const float* x   = (const float*)d_in[0];
    const float* emb = (const float*)d_in[1];
    float* out = (float*)d_out;

    cudaFuncSetAttribute(vq_mma_kernel, cudaFuncAttributeMaxDynamicSharedMemorySize, DYN_SMEM);

    cnorm_kernel<<<KCODE / 8, 256>>>(emb);
    vq_mma_kernel<<<NTOK / BM, 256, DYN_SMEM>>>(x, emb, out);
}

// round 6
// speedup vs baseline: 1.0507x; 1.0507x over previous
#include <cuda_runtime.h>
#include <cstdint>

// VQ nearest-codebook lookup via 3xTF32 mma.sync distance GEMM.
//   z_e_x: [16,2048,256] f32 -> N=32768 rows, D=256
//   embedding: [1024,256] f32 -> K=1024 codes
// d_out (f32): z_q_x [N*D] @0, z_q_x_bar [N*D] @8388608, indices [N] @16777216
// argmax_k(x.c - ||c||^2/2). Hi/lo tf32 split done at store (as R4, rel_err 0.0),
// double-buffered smem stages so split/store overlaps mma (fixes R4's 56% duty).

#define NTOK   32768
#define DDIM   256
#define KCODE  1024
#define BM     256          // rows per CTA
#define BN     128          // codes per tile
#define KS     16           // k per stage
#define NST    16           // stages per tile
#define NTILE  8            // KCODE / BN
#define NG     (NTILE * NST)
#define PITCH  20           // floats per k16 row (80B, bank/ldsm-clean)

#define OUT_BAR   8388608
#define OUT_IDX  16777216

// float offsets into dynamic smem (double-buffered hi/lo tiles)
#define A_STAGE  (BM * PITCH)           // 5120
#define B_STAGE  (BN * PITCH)           // 2560
#define AH_F      0                     // 2 x [256][20]
#define AL_F  (2 * A_STAGE)             // 10240
#define BH_F  (4 * A_STAGE)             // 20480: 2 x [128][20]
#define BL_F  (BH_F + 2 * B_STAGE)      // 25600
#define CN_F  (BL_F + 2 * B_STAGE)      // 30720
#define DYN_FLOATS (CN_F + KCODE)       // 31744
#define DYN_SMEM (DYN_FLOATS * 4)       // 126976 B

__device__ float g_cnorm[KCODE];

// ---------------------------------------------------------------------------
__device__ __forceinline__ uint32_t smem_u32(const void* p) {
    uint32_t a;
    asm("{ .reg .u64 t; cvta.to.shared.u64 t, %1; cvt.u32.u64 %0, t; }"
        : "=r"(a) : "l"(p));
    return a;
}
__device__ __forceinline__ float tf32_rna(float x) {
    uint32_t r;
    asm("cvt.rna.tf32.f32 %0, %1;" : "=r"(r) : "f"(x));
    return __uint_as_float(r);
}
#define LDSM4(r, addr) \
    asm volatile("ldmatrix.sync.aligned.m8n8.x4.shared.b16 {%0,%1,%2,%3}, [%4];" \
        : "=r"((r)[0]), "=r"((r)[1]), "=r"((r)[2]), "=r"((r)[3]) : "r"(addr))

__device__ __forceinline__ void mma_tf32(float* c, const uint32_t* a, const uint32_t* b) {
    asm volatile(
        "mma.sync.aligned.m16n8k8.row.col.f32.tf32.tf32.f32 "
        "{%0,%1,%2,%3}, {%4,%5,%6,%7}, {%8,%9}, {%0,%1,%2,%3};"
        : "+f"(c[0]), "+f"(c[1]), "+f"(c[2]), "+f"(c[3])
        : "r"(a[0]), "r"(a[1]), "r"(a[2]), "r"(a[3]), "r"(b[0]), "r"(b[1]));
}

// ---------------------------------------------------------------------------
__global__ void cnorm_kernel(const float* __restrict__ emb) {
    int warp = (blockIdx.x * blockDim.x + threadIdx.x) >> 5;
    int lane = threadIdx.x & 31;
    if (warp >= KCODE) return;
    const float* row = emb + (size_t)warp * DDIM;
    float s = 0.f;
    #pragma unroll
    for (int k = lane; k < DDIM; k += 32) { float v = row[k]; s += v * v; }
    #pragma unroll
    for (int o = 16; o; o >>= 1) s += __shfl_xor_sync(0xffffffffu, s, o);
    if (lane == 0) g_cnorm[warp] = s;
}

// ---------------------------------------------------------------------------
// 256 threads = 8 warps in 4(m) x 2(n); warp tile 64 rows x 64 codes.
// ---------------------------------------------------------------------------
__global__ __launch_bounds__(256)
void vq_mma_kernel(const float* __restrict__ x,
                   const float* __restrict__ emb,
                   float* __restrict__ out) {
    extern __shared__ float dsm[];
    __shared__ float sV[2][BM];
    __shared__ int   sI[2][BM];
    __shared__ int   bidx_s[BM];

    const int tid = threadIdx.x;
    const int wid = tid >> 5;
    const int L   = tid & 31;
    const int rowBase = blockIdx.x * BM;
    const int mbase = (wid >> 1) * 64;
    const int nbase = (wid & 1) * 64;

    const uint32_t SB = smem_u32(dsm);

    // ldmatrix lane geometry (byte offsets within a stage tile)
    const int aRow = (L & 7) + 8 * ((L >> 3) & 1);
    const int aK   = (L >> 4) * 16;
    const int bRow = (L & 7) + 8 * ((L >> 4) & 1);
    const int bK   = ((L >> 3) & 1) * 16;
    const uint32_t aBase = (uint32_t)((mbase + aRow) * 80 + aK);
    const uint32_t bBase = (uint32_t)((nbase + bRow) * 80 + bK);

    // loader geometry
    const int lRow = tid >> 2;          // 0..63
    const int lKg  = tid & 3;           // float4 slot within k16

    // cnorm table into smem (once)
    #pragma unroll
    for (int i = 0; i < 4; ++i) dsm[CN_F + tid + 256 * i] = g_cnorm[tid + 256 * i];

    float bV[8];
    int   bI[8];
    #pragma unroll
    for (int i = 0; i < 8; ++i) { bV[i] = -3.4e38f; bI[i] = 0x7fffffff; }

    float4 vA[4], vB[2];

    // ---- LDG registers for global stage sidx ----
    #define LOAD_STAGE(sidx) do { \
        const int _t  = (sidx) >> 4; \
        const int _ko = ((sidx) & 15) * KS + lKg * 4; \
        const float* xp = x + (size_t)(rowBase + lRow) * DDIM + _ko; \
        vA[0] = *(const float4*)(xp); \
        vA[1] = *(const float4*)(xp +  64 * DDIM); \
        vA[2] = *(const float4*)(xp + 128 * DDIM); \
        vA[3] = *(const float4*)(xp + 192 * DDIM); \
        const float* bp = emb + (size_t)(_t * BN + lRow) * DDIM + _ko; \
        vB[0] = *(const float4*)(bp); \
        vB[1] = *(const float4*)(bp + 64 * DDIM); \
    } while (0)

    #define STORE_A(buf) do { \
        _Pragma("unroll") \
        for (int _i = 0; _i < 4; ++_i) { \
            float4 v = vA[_i]; float4 h, l; \
            h.x = tf32_rna(v.x); l.x = tf32_rna(v.x - h.x); \
            h.y = tf32_rna(v.y); l.y = tf32_rna(v.y - h.y); \
            h.z = tf32_rna(v.z); l.z = tf32_rna(v.z - h.z); \
            h.w = tf32_rna(v.w); l.w = tf32_rna(v.w - h.w); \
            int r = lRow + 64 * _i; \
            *(float4*)&dsm[AH_F + (buf) * A_STAGE + r * PITCH + lKg * 4] = h; \
            *(float4*)&dsm[AL_F + (buf) * A_STAGE + r * PITCH + lKg * 4] = l; \
        } \
    } while (0)

    #define STORE_B(buf) do { \
        _Pragma("unroll") \
        for (int _i = 0; _i < 2; ++_i) { \
            float4 v = vB[_i]; float4 h, l; \
            h.x = tf32_rna(v.x); l.x = tf32_rna(v.x - h.x); \
            h.y = tf32_rna(v.y); l.y = tf32_rna(v.y - h.y); \
            h.z = tf32_rna(v.z); l.z = tf32_rna(v.z - h.z); \
            h.w = tf32_rna(v.w); l.w = tf32_rna(v.w - h.w); \
            int r = lRow + 64 * _i; \
            *(float4*)&dsm[BH_F + (buf) * B_STAGE + r * PITCH + lKg * 4] = h; \
            *(float4*)&dsm[BL_F + (buf) * B_STAGE + r * PITCH + lKg * 4] = l; \
        } \
    } while (0)

    float acc[4][8][4];
    #pragma unroll
    for (int f = 0; f < 4; ++f)
        #pragma unroll
        for (int n = 0; n < 8; ++n)
            #pragma unroll
            for (int e = 0; e < 4; ++e) acc[f][n][e] = 0.f;

    // prologue: stage 0 into buffer 0
    LOAD_STAGE(0);
    STORE_A(0);
    STORE_B(0);
    __syncthreads();

    for (int g = 0; g < NG; ++g) {
        const int buf = g & 1;
        const uint32_t AHB = SB + (AH_F + buf * A_STAGE) * 4;
        const uint32_t ALB = SB + (AL_F + buf * A_STAGE) * 4;
        const uint32_t BHB = SB + (BH_F + buf * B_STAGE) * 4;
        const uint32_t BLB = SB + (BL_F + buf * B_STAGE) * 4;

        if (g + 1 < NG) LOAD_STAGE(g + 1);   // LDG in flight under kk0 mma

        // ---- kk = 0 ----
        {
            uint32_t ah[4][4], bh[4][4], bl[4][4], al[4][4];
            #pragma unroll
            for (int f = 0; f < 4; ++f) LDSM4(ah[f], AHB + aBase + f * 1280);
            #pragma unroll
            for (int q = 0; q < 4; ++q) LDSM4(bh[q], BHB + bBase + q * 1280);
            #pragma unroll
            for (int f = 0; f < 4; ++f)
                #pragma unroll
                for (int n = 0; n < 8; ++n)
                    mma_tf32(acc[f][n], ah[f], &bh[n >> 1][(n & 1) * 2]);
            #pragma unroll
            for (int q = 0; q < 4; ++q) LDSM4(bl[q], BLB + bBase + q * 1280);
            #pragma unroll
            for (int f = 0; f < 4; ++f)
                #pragma unroll
                for (int n = 0; n < 8; ++n)
                    mma_tf32(acc[f][n], ah[f], &bl[n >> 1][(n & 1) * 2]);
            #pragma unroll
            for (int f = 0; f < 4; ++f) LDSM4(al[f], ALB + aBase + f * 1280);
            #pragma unroll
            for (int f = 0; f < 4; ++f)
                #pragma unroll
                for (int n = 0; n < 8; ++n)
                    mma_tf32(acc[f][n], al[f], &bh[n >> 1][(n & 1) * 2]);
        }

        if (g + 1 < NG) STORE_A(buf ^ 1);    // overlap store with tensor drain

        // ---- kk = 1 ----
        {
            uint32_t ah[4][4], bh[4][4], bl[4][4], al[4][4];
            #pragma unroll
            for (int f = 0; f < 4; ++f) LDSM4(ah[f], AHB + aBase + f * 1280 + 32);
            #pragma unroll
            for (int q = 0; q < 4; ++q) LDSM4(bh[q], BHB + bBase + q * 1280 + 32);
            #pragma unroll
            for (int f = 0; f < 4; ++f)
                #pragma unroll
                for (int n = 0; n < 8; ++n)
                    mma_tf32(acc[f][n], ah[f], &bh[n >> 1][(n & 1) * 2]);
            #pragma unroll
            for (int q = 0; q < 4; ++q) LDSM4(bl[q], BLB + bBase + q * 1280 + 32);
            #pragma unroll
            for (int f = 0; f < 4; ++f)
                #pragma unroll
                for (int n = 0; n < 8; ++n)
                    mma_tf32(acc[f][n], ah[f], &bl[n >> 1][(n & 1) * 2]);
            #pragma unroll
            for (int f = 0; f < 4; ++f) LDSM4(al[f], ALB + aBase + f * 1280 + 32);
            #pragma unroll
            for (int f = 0; f < 4; ++f)
                #pragma unroll
                for (int n = 0; n < 8; ++n)
                    mma_tf32(acc[f][n], al[f], &bh[n >> 1][(n & 1) * 2]);
        }

        if (g + 1 < NG) STORE_B(buf ^ 1);

        // ---- tile epilogue: fold norms, update per-lane argmax ----
        if ((g & 15) == 15) {
            const int cb = (g >> 4) * BN;
            #pragma unroll
            for (int n = 0; n < 8; ++n) {
                #pragma unroll
                for (int e = 0; e < 2; ++e) {
                    const int ci = cb + nbase + 8 * n + 2 * (L & 3) + e;
                    const float hc = -0.5f * dsm[CN_F + ci];
                    #pragma unroll
                    for (int f = 0; f < 4; ++f) {
                        float vlo = acc[f][n][e]     + hc;
                        float vhi = acc[f][n][2 + e] + hc;
                        if (vlo > bV[2 * f])     { bV[2 * f] = vlo;     bI[2 * f] = ci; }
                        if (vhi > bV[2 * f + 1]) { bV[2 * f + 1] = vhi; bI[2 * f + 1] = ci; }
                    }
                }
            }
            if (g + 1 < NG) {
                #pragma unroll
                for (int f = 0; f < 4; ++f)
                    #pragma unroll
                    for (int n = 0; n < 8; ++n)
                        #pragma unroll
                        for (int e = 0; e < 4; ++e) acc[f][n][e] = 0.f;
            }
        }
        __syncthreads();
    }

    // quad reduce (lanes sharing L>>2 cover the same rows)
    #pragma unroll
    for (int i = 0; i < 8; ++i) {
        float v = bV[i]; int idx = bI[i];
        #pragma unroll
        for (int o = 1; o < 4; o <<= 1) {
            float vo = __shfl_xor_sync(0xffffffffu, v, o);
            int   io = __shfl_xor_sync(0xffffffffu, idx, o);
            if (vo > v || (vo == v && io < idx)) { v = vo; idx = io; }
        }
        bV[i] = v; bI[i] = idx;
    }
    if ((L & 3) == 0) {
        const int wn = wid & 1;
        #pragma unroll
        for (int f = 0; f < 4; ++f)
            #pragma unroll
            for (int h = 0; h < 2; ++h) {
                int row = mbase + 16 * f + 8 * h + (L >> 2);
                sV[wn][row] = bV[2 * f + h];
                sI[wn][row] = bI[2 * f + h];
            }
    }
    __syncthreads();

    // combine the two n-warps, publish winners
    {
        float v0 = sV[0][tid], v1 = sV[1][tid];
        int   i0 = sI[0][tid], i1 = sI[1][tid];
        int idx = (v1 > v0 || (v1 == v0 && i1 < i0)) ? i1 : i0;
        bidx_s[tid] = idx;
        out[OUT_IDX + rowBase + tid] = (float)idx;
    }
    __syncthreads();

    // gather codes, write z_q_x and z_q_x_bar
    const float4* emb4 = (const float4*)emb;
    float4* o4 = (float4*)out;
    #pragma unroll 4
    for (int it = 0; it < 64; ++it) {
        int g = tid + it * 256;          // 0..16383
        int m = g >> 6;
        int q = g & 63;
        int code = bidx_s[m];
        float4 v = emb4[(size_t)code * 64 + q];
        size_t off = (size_t)(rowBase + m) * 64 + q;
        o4[off] = v;
        o4[off + (OUT_BAR / 4)] = v;
    }
}

// ---------------------------------------------------------------------------
extern "C" void kernel_launch(void* const* d_in, const int* in_sizes, int n_in,
                              void* d_out, int out_size) {
    const float* x   = (const float*)d_in[0];
    const float* emb = (const float*)d_in[1];
    float* out = (float*)d_out;

    cudaFuncSetAttribute(vq_mma_kernel, cudaFuncAttributeMaxDynamicSharedMemorySize, DYN_SMEM);

    cnorm_kernel<<<KCODE / 8, 256>>>(emb);
    vq_mma_kernel<<<NTOK / BM, 256, DYN_SMEM>>>(x, emb, out);
}

// round 7
// speedup vs baseline: 1.0780x; 1.0259x over previous
#include <cuda_runtime.h>
#include <cstdint>

// VQ nearest-codebook lookup via 3xTF32 mma.sync distance GEMM.
//   z_e_x: [16,2048,256] f32 -> N=32768 rows, D=256
//   embedding: [1024,256] f32 -> K=1024 codes
// d_out (f32): z_q_x [N*D] @0, z_q_x_bar [N*D] @8388608, indices [N] @16777216
// argmax_k(x.c - ||c||^2/2). tf32 hi/lo split at store (rel_err 0.0 lineage).
// R7: BM=128, warp tile 32x64, <=128 regs, 2 CTAs/SM for latency hiding.

#define NTOK   32768
#define DDIM   256
#define KCODE  1024
#define BM     128          // rows per CTA
#define BN     128          // codes per tile
#define KS     16           // k per stage
#define NST    16           // stages per tile
#define NTILE  8            // KCODE / BN
#define NG     (NTILE * NST)
#define PITCH  20           // floats per k16 row (80B, bank/ldsm-clean)

#define OUT_BAR   8388608
#define OUT_IDX  16777216

// float offsets into dynamic smem (double-buffered hi/lo tiles)
#define A_STAGE  (BM * PITCH)           // 2560
#define B_STAGE  (BN * PITCH)           // 2560
#define AH_F      0                     // 2 x [128][20]
#define AL_F  (2 * A_STAGE)
#define BH_F  (4 * A_STAGE)
#define BL_F  (BH_F + 2 * B_STAGE)
#define CN_F  (BL_F + 2 * B_STAGE)      // 20480
#define DYN_FLOATS (CN_F + KCODE)       // 21504
#define DYN_SMEM (DYN_FLOATS * 4)       // 86016 B

__device__ float g_cnorm[KCODE];

// ---------------------------------------------------------------------------
__device__ __forceinline__ uint32_t smem_u32(const void* p) {
    uint32_t a;
    asm("{ .reg .u64 t; cvta.to.shared.u64 t, %1; cvt.u32.u64 %0, t; }"
        : "=r"(a) : "l"(p));
    return a;
}
__device__ __forceinline__ float tf32_rna(float x) {
    uint32_t r;
    asm("cvt.rna.tf32.f32 %0, %1;" : "=r"(r) : "f"(x));
    return __uint_as_float(r);
}
#define LDSM4(r, addr) \
    asm volatile("ldmatrix.sync.aligned.m8n8.x4.shared.b16 {%0,%1,%2,%3}, [%4];" \
        : "=r"((r)[0]), "=r"((r)[1]), "=r"((r)[2]), "=r"((r)[3]) : "r"(addr))

__device__ __forceinline__ void mma_tf32(float* c, const uint32_t* a, const uint32_t* b) {
    asm volatile(
        "mma.sync.aligned.m16n8k8.row.col.f32.tf32.tf32.f32 "
        "{%0,%1,%2,%3}, {%4,%5,%6,%7}, {%8,%9}, {%0,%1,%2,%3};"
        : "+f"(c[0]), "+f"(c[1]), "+f"(c[2]), "+f"(c[3])
        : "r"(a[0]), "r"(a[1]), "r"(a[2]), "r"(a[3]), "r"(b[0]), "r"(b[1]));
}

// ---------------------------------------------------------------------------
__global__ void cnorm_kernel(const float* __restrict__ emb) {
    int warp = (blockIdx.x * blockDim.x + threadIdx.x) >> 5;
    int lane = threadIdx.x & 31;
    if (warp >= KCODE) return;
    const float* row = emb + (size_t)warp * DDIM;
    float s = 0.f;
    #pragma unroll
    for (int k = lane; k < DDIM; k += 32) { float v = row[k]; s += v * v; }
    #pragma unroll
    for (int o = 16; o; o >>= 1) s += __shfl_xor_sync(0xffffffffu, s, o);
    if (lane == 0) g_cnorm[warp] = s;
}

// ---------------------------------------------------------------------------
// 256 threads = 8 warps in 4(m) x 2(n); warp tile 32 rows x 64 codes.
// ---------------------------------------------------------------------------
__global__ __launch_bounds__(256, 2)
void vq_mma_kernel(const float* __restrict__ x,
                   const float* __restrict__ emb,
                   float* __restrict__ out) {
    extern __shared__ float dsm[];
    __shared__ float sV[2][BM];
    __shared__ int   sI[2][BM];
    __shared__ int   bidx_s[BM];

    const int tid = threadIdx.x;
    const int wid = tid >> 5;
    const int L   = tid & 31;
    const int rowBase = blockIdx.x * BM;
    const int mbase = (wid >> 1) * 32;       // 0/32/64/96
    const int nbase = (wid & 1) * 64;        // 0/64

    const uint32_t SB = smem_u32(dsm);

    // ldmatrix lane geometry (byte offsets within a stage tile)
    const int aRow = (L & 7) + 8 * ((L >> 3) & 1);
    const int aK   = (L >> 4) * 16;
    const int bRow = (L & 7) + 8 * ((L >> 4) & 1);
    const int bK   = ((L >> 3) & 1) * 16;
    const uint32_t aBase = (uint32_t)((mbase + aRow) * 80 + aK);
    const uint32_t bBase = (uint32_t)((nbase + bRow) * 80 + bK);

    // loader geometry: rows lRow and lRow+64, float4 slot lKg
    const int lRow = tid >> 2;          // 0..63
    const int lKg  = tid & 3;

    // cnorm table into smem (once)
    #pragma unroll
    for (int i = 0; i < 4; ++i) dsm[CN_F + tid + 256 * i] = g_cnorm[tid + 256 * i];

    float bV[4];
    int   bI[4];
    #pragma unroll
    for (int i = 0; i < 4; ++i) { bV[i] = -3.4e38f; bI[i] = 0x7fffffff; }

    float4 vA[2], vB[2];

    #define LOAD_STAGE(sidx) do { \
        const int _t  = (sidx) >> 4; \
        const int _ko = ((sidx) & 15) * KS + lKg * 4; \
        const float* xp = x + (size_t)(rowBase + lRow) * DDIM + _ko; \
        vA[0] = *(const float4*)(xp); \
        vA[1] = *(const float4*)(xp + 64 * DDIM); \
        const float* bp = emb + (size_t)(_t * BN + lRow) * DDIM + _ko; \
        vB[0] = *(const float4*)(bp); \
        vB[1] = *(const float4*)(bp + 64 * DDIM); \
    } while (0)

    #define STORE_A(buf) do { \
        _Pragma("unroll") \
        for (int _i = 0; _i < 2; ++_i) { \
            float4 v = vA[_i]; float4 h, l; \
            h.x = tf32_rna(v.x); l.x = tf32_rna(v.x - h.x); \
            h.y = tf32_rna(v.y); l.y = tf32_rna(v.y - h.y); \
            h.z = tf32_rna(v.z); l.z = tf32_rna(v.z - h.z); \
            h.w = tf32_rna(v.w); l.w = tf32_rna(v.w - h.w); \
            int r = lRow + 64 * _i; \
            *(float4*)&dsm[AH_F + (buf) * A_STAGE + r * PITCH + lKg * 4] = h; \
            *(float4*)&dsm[AL_F + (buf) * A_STAGE + r * PITCH + lKg * 4] = l; \
        } \
    } while (0)

    #define STORE_B(buf) do { \
        _Pragma("unroll") \
        for (int _i = 0; _i < 2; ++_i) { \
            float4 v = vB[_i]; float4 h, l; \
            h.x = tf32_rna(v.x); l.x = tf32_rna(v.x - h.x); \
            h.y = tf32_rna(v.y); l.y = tf32_rna(v.y - h.y); \
            h.z = tf32_rna(v.z); l.z = tf32_rna(v.z - h.z); \
            h.w = tf32_rna(v.w); l.w = tf32_rna(v.w - h.w); \
            int r = lRow + 64 * _i; \
            *(float4*)&dsm[BH_F + (buf) * B_STAGE + r * PITCH + lKg * 4] = h; \
            *(float4*)&dsm[BL_F + (buf) * B_STAGE + r * PITCH + lKg * 4] = l; \
        } \
    } while (0)

    float acc[2][8][4];
    #pragma unroll
    for (int f = 0; f < 2; ++f)
        #pragma unroll
        for (int n = 0; n < 8; ++n)
            #pragma unroll
            for (int e = 0; e < 4; ++e) acc[f][n][e] = 0.f;

    // prologue: stage 0 into buffer 0
    LOAD_STAGE(0);
    STORE_A(0);
    STORE_B(0);
    __syncthreads();

    for (int g = 0; g < NG; ++g) {
        const int buf = g & 1;
        const uint32_t AHB = SB + (AH_F + buf * A_STAGE) * 4;
        const uint32_t ALB = SB + (AL_F + buf * A_STAGE) * 4;
        const uint32_t BHB = SB + (BH_F + buf * B_STAGE) * 4;
        const uint32_t BLB = SB + (BL_F + buf * B_STAGE) * 4;

        if (g + 1 < NG) LOAD_STAGE(g + 1);

        #pragma unroll
        for (int kk = 0; kk < 2; ++kk) {
            const uint32_t kof = (uint32_t)(kk * 32);
            uint32_t ah[2][4], al[2][4], bh[4][4], bl[4][4];
            #pragma unroll
            for (int f = 0; f < 2; ++f) LDSM4(ah[f], AHB + aBase + f * 1280 + kof);
            #pragma unroll
            for (int q = 0; q < 4; ++q) LDSM4(bh[q], BHB + bBase + q * 1280 + kof);
            #pragma unroll
            for (int f = 0; f < 2; ++f)
                #pragma unroll
                for (int n = 0; n < 8; ++n)
                    mma_tf32(acc[f][n], ah[f], &bh[n >> 1][(n & 1) * 2]);
            #pragma unroll
            for (int q = 0; q < 4; ++q) LDSM4(bl[q], BLB + bBase + q * 1280 + kof);
            #pragma unroll
            for (int f = 0; f < 2; ++f)
                #pragma unroll
                for (int n = 0; n < 8; ++n)
                    mma_tf32(acc[f][n], ah[f], &bl[n >> 1][(n & 1) * 2]);
            #pragma unroll
            for (int f = 0; f < 2; ++f) LDSM4(al[f], ALB + aBase + f * 1280 + kof);
            #pragma unroll
            for (int f = 0; f < 2; ++f)
                #pragma unroll
                for (int n = 0; n < 8; ++n)
                    mma_tf32(acc[f][n], al[f], &bh[n >> 1][(n & 1) * 2]);

            // overlap next-stage split/store with tensor drain
            if (kk == 0) { if (g + 1 < NG) STORE_A(buf ^ 1); }
            else         { if (g + 1 < NG) STORE_B(buf ^ 1); }
        }

        // ---- tile epilogue: fold norms, update per-lane argmax ----
        if ((g & 15) == 15) {
            const int cb = (g >> 4) * BN;
            #pragma unroll
            for (int n = 0; n < 8; ++n) {
                #pragma unroll
                for (int e = 0; e < 2; ++e) {
                    const int ci = cb + nbase + 8 * n + 2 * (L & 3) + e;
                    const float hc = -0.5f * dsm[CN_F + ci];
                    #pragma unroll
                    for (int f = 0; f < 2; ++f) {
                        float vlo = acc[f][n][e]     + hc;
                        float vhi = acc[f][n][2 + e] + hc;
                        if (vlo > bV[2 * f])     { bV[2 * f] = vlo;     bI[2 * f] = ci; }
                        if (vhi > bV[2 * f + 1]) { bV[2 * f + 1] = vhi; bI[2 * f + 1] = ci; }
                    }
                }
            }
            if (g + 1 < NG) {
                #pragma unroll
                for (int f = 0; f < 2; ++f)
                    #pragma unroll
                    for (int n = 0; n < 8; ++n)
                        #pragma unroll
                        for (int e = 0; e < 4; ++e) acc[f][n][e] = 0.f;
            }
        }
        __syncthreads();
    }

    // quad reduce (lanes sharing L>>2 cover the same rows)
    #pragma unroll
    for (int i = 0; i < 4; ++i) {
        float v = bV[i]; int idx = bI[i];
        #pragma unroll
        for (int o = 1; o < 4; o <<= 1) {
            float vo = __shfl_xor_sync(0xffffffffu, v, o);
            int   io = __shfl_xor_sync(0xffffffffu, idx, o);
            if (vo > v || (vo == v && io < idx)) { v = vo; idx = io; }
        }
        bV[i] = v; bI[i] = idx;
    }
    if ((L & 3) == 0) {
        const int wn = wid & 1;
        #pragma unroll
        for (int f = 0; f < 2; ++f)
            #pragma unroll
            for (int h = 0; h < 2; ++h) {
                int row = mbase + 16 * f + 8 * h + (L >> 2);
                sV[wn][row] = bV[2 * f + h];
                sI[wn][row] = bI[2 * f + h];
            }
    }
    __syncthreads();

    // combine the two n-warps, publish winners
    if (tid < BM) {
        float v0 = sV[0][tid], v1 = sV[1][tid];
        int   i0 = sI[0][tid], i1 = sI[1][tid];
        int idx = (v1 > v0 || (v1 == v0 && i1 < i0)) ? i1 : i0;
        bidx_s[tid] = idx;
        out[OUT_IDX + rowBase + tid] = (float)idx;
    }
    __syncthreads();

    // gather codes, write z_q_x and z_q_x_bar
    const float4* emb4 = (const float4*)emb;
    float4* o4 = (float4*)out;
    #pragma unroll 4
    for (int it = 0; it < 32; ++it) {
        int g = tid + it * 256;          // 0..8191
        int m = g >> 6;                  // 0..127
        int q = g & 63;
        int code = bidx_s[m];
        float4 v = emb4[(size_t)code * 64 + q];
        size_t off = (size_t)(rowBase + m) * 64 + q;
        o4[off] = v;
        o4[off + (OUT_BAR / 4)] = v;
    }
}

// ---------------------------------------------------------------------------
extern "C" void kernel_launch(void* const* d_in, const int* in_sizes, int n_in,
                              void* d_out, int out_size) {
    const float* x   = (const float*)d_in[0];
    const float* emb = (const float*)d_in[1];
    float* out = (float*)d_out;

    cudaFuncSetAttribute(vq_mma_kernel, cudaFuncAttributeMaxDynamicSharedMemorySize, DYN_SMEM);

    cnorm_kernel<<<KCODE / 8, 256>>>(emb);
    vq_mma_kernel<<<NTOK / BM, 256, DYN_SMEM>>>(x, emb, out);
}